// round 17
// baseline (speedup 1.0000x reference)
#include <cuda_runtime.h>
#include <cuda_fp16.h>
#include <math.h>
#include <stdint.h>

#define MSG_DIM 100
#define MEM_DIM 172
#define KDIM    272
#define JPAD    176
#define MROWS   64             // update rows per CTA
#define NTH     128
#define KSTEPS  17             // 272 / 16
#define NJC     22             // 176 / 8 col-chunks
#define XSTR    280            // fp16 elems per x row (560 B)
#define NFRAG   (NJC * KSTEPS * 2 * 32)
#define MASK_CAP (4u << 20)

// ---------------- persistent scratch ----------------
// uint4 = two fp16 gate fragments: p=0:{R,Z} p=1:{I,H}
__device__ __align__(16) uint4 g_Wf[NFRAG];
__device__ float g_bias[4 * JPAD];   // br, bz, bi, bh
__device__ unsigned char g_mask[MASK_CAP];

// ---------------- smem layout (bytes) ----------------
#define SM_NID 0
#define SM_TS  256
#define SM_XH  1024
#define SM_TOT (SM_XH + MROWS * XSTR * 2)     // 36864 -> 4 CTAs/SM

// ---------------- helpers ----------------
__device__ __forceinline__ uint32_t smem_u32(const void* p) {
    uint32_t a;
    asm("{ .reg .u64 t; cvta.to.shared.u64 t, %1; cvt.u32.u64 %0, t; }" : "=r"(a) : "l"(p));
    return a;
}
#define LDSM4(r0, r1, r2, r3, addr) \
    asm volatile("ldmatrix.sync.aligned.m8n8.x4.shared.b16 {%0,%1,%2,%3}, [%4];" \
                 : "=r"(r0), "=r"(r1), "=r"(r2), "=r"(r3) : "r"(addr))
#define MMA(d, a, b0, b1) \
    asm volatile("mma.sync.aligned.m16n8k16.row.col.f32.f16.f16.f32 " \
                 "{%0,%1,%2,%3}, {%4,%5,%6,%7}, {%8,%9}, {%0,%1,%2,%3};" \
                 : "+f"((d)[0]), "+f"((d)[1]), "+f"((d)[2]), "+f"((d)[3]) \
                 : "r"((a)[0]), "r"((a)[1]), "r"((a)[2]), "r"((a)[3]), \
                   "r"(b0), "r"(b1))

__device__ __forceinline__ float wval(int plane, int n, int k,
                                      const float* __restrict__ W_ih,
                                      const float* __restrict__ W_hh) {
    if (n >= MEM_DIM || k >= KDIM) return 0.f;
    if (plane == 0)
        return (k < MSG_DIM) ? W_ih[n * MSG_DIM + k]
                             : W_hh[n * MEM_DIM + (k - MSG_DIM)];
    if (plane == 1)
        return (k < MSG_DIM) ? W_ih[(MEM_DIM + n) * MSG_DIM + k]
                             : W_hh[(MEM_DIM + n) * MEM_DIM + (k - MSG_DIM)];
    if (plane == 2)
        return (k < MSG_DIM) ? W_ih[(2 * MEM_DIM + n) * MSG_DIM + k] : 0.f;
    return (k >= MSG_DIM) ? W_hh[(2 * MEM_DIM + n) * MEM_DIM + (k - MSG_DIM)] : 0.f;
}
__device__ __forceinline__ uint32_t pack_h(float a, float b) {
    __half2 v = __floats2half2_rn(a, b);
    return *(uint32_t*)&v;                // low 16 = a
}

// ---------------------------------------------------------------------------
// Prep: build paired fp16 B fragments + bias. (R15 layout, validated.)
// ---------------------------------------------------------------------------
__global__ void prep_kernel(const float* __restrict__ W_ih,
                            const float* __restrict__ W_hh,
                            const float* __restrict__ b_ih,
                            const float* __restrict__ b_hh) {
    int idx = blockIdx.x * blockDim.x + threadIdx.x;
    if (idx < NFRAG) {
        int lane = idx & 31;
        int rest = idx >> 5;
        int p    = rest & 1;
        rest >>= 1;
        int ks   = rest % KSTEPS;
        int jc   = rest / KSTEPS;
        int planeA = p * 2;                // 0 (R) or 2 (I)
        int planeB = planeA + 1;           // 1 (Z) or 3 (H)
        int n  = jc * 8 + (lane >> 2);
        int kb = ks * 16 + (lane & 3) * 2;
        float a00 = wval(planeA, n, kb + 0, W_ih, W_hh);
        float a01 = wval(planeA, n, kb + 1, W_ih, W_hh);
        float a10 = wval(planeA, n, kb + 8, W_ih, W_hh);
        float a11 = wval(planeA, n, kb + 9, W_ih, W_hh);
        float b00 = wval(planeB, n, kb + 0, W_ih, W_hh);
        float b01 = wval(planeB, n, kb + 1, W_ih, W_hh);
        float b10 = wval(planeB, n, kb + 8, W_ih, W_hh);
        float b11 = wval(planeB, n, kb + 9, W_ih, W_hh);
        g_Wf[idx] = make_uint4(pack_h(a00, a01), pack_h(a10, a11),
                               pack_h(b00, b01), pack_h(b10, b11));
    }
    if (idx < JPAD) {
        int j = idx;
        float br = 0.f, bz = 0.f, bi = 0.f, bh = 0.f;
        if (j < MEM_DIM) {
            br = b_ih[j]               + b_hh[j];
            bz = b_ih[MEM_DIM + j]     + b_hh[MEM_DIM + j];
            bi = b_ih[2 * MEM_DIM + j];
            bh = b_hh[2 * MEM_DIM + j];
        }
        g_bias[j]            = br;
        g_bias[JPAD + j]     = bz;
        g_bias[2 * JPAD + j] = bi;
        g_bias[3 * JPAD + j] = bh;
    }
}

__global__ void mask_kernel(const int* __restrict__ node_ids, int n_upd) {
    int i = blockIdx.x * blockDim.x + threadIdx.x;
    if (i < n_upd) {
        int nid = node_ids[i];
        if (nid >= 0 && (unsigned)nid < MASK_CAP) g_mask[nid] = 1;
    }
}

// ---------------------------------------------------------------------------
// Copies. Masked variants skip updated rows (GRU writes them concurrently).
// ---------------------------------------------------------------------------
__global__ void copy_mem_masked(const float4* __restrict__ src,
                                float4* __restrict__ dst, long long n4) {
    long long i = (long long)blockIdx.x * blockDim.x + threadIdx.x;
    if (i < n4) {
        unsigned row = (unsigned)(i / (MEM_DIM / 4));
        if (!g_mask[row]) dst[i] = src[i];
    }
}
__global__ void copy_lu_masked(const float* __restrict__ src,
                               float* __restrict__ dst, long long n) {
    long long i = (long long)blockIdx.x * blockDim.x + threadIdx.x;
    if (i < n) {
        if (!g_mask[i]) dst[i] = src[i];
    }
}
// Unmasked fallback (serial path)
__global__ void copy_kernel(const float* __restrict__ src, float* __restrict__ dst, long long n) {
    long long i = (long long)blockIdx.x * blockDim.x + threadIdx.x;
    long long n4 = n >> 2;
    if (i < n4) ((float4*)dst)[i] = ((const float4*)src)[i];
    long long tail = n & 3;
    if (i < tail) dst[n4 * 4 + i] = src[n4 * 4 + i];
}

// ---------------------------------------------------------------------------
// GRU via mma.sync fp16 single-pass (R16, unchanged).
// ---------------------------------------------------------------------------
__global__ void __launch_bounds__(NTH, 4)
gru_mma_kernel(const int*   __restrict__ node_ids,
               const float* __restrict__ messages,
               const float* __restrict__ timestamps,
               const float* __restrict__ memory,
               float*       __restrict__ out,
               int n_upd, long long n_nodes)
{
    extern __shared__ __align__(16) char smc[];
    int*   s_nid = (int*)(smc + SM_NID);
    float* s_ts  = (float*)(smc + SM_TS);
    __half* xh = (__half*)(smc + SM_XH);
    const uint32_t smb = smem_u32(smc);

    const int tid  = threadIdx.x;
    const int lane = tid & 31;
    const int wid  = tid >> 5;
    const int row0 = blockIdx.x * MROWS;

    if (tid < MROWS) {
        int r = row0 + tid;
        if (r < n_upd) { s_nid[tid] = node_ids[r]; s_ts[tid] = timestamps[r]; }
        else           { s_nid[tid] = -1;          s_ts[tid] = 0.f; }
    }
    __syncthreads();

    // last_update scatter
    if (tid < MROWS && s_nid[tid] >= 0)
        out[n_nodes * (long long)MEM_DIM + s_nid[tid]] = s_ts[tid];

    // ---- gather x rows as fp16 ----
    for (int idx = tid; idx < MROWS * (XSTR / 2); idx += NTH) {
        int r  = idx / (XSTR / 2);
        int k  = (idx - r * (XSTR / 2)) * 2;
        float x0 = 0.f, x1 = 0.f;
        int nid = s_nid[r];
        if (nid >= 0) {
            long long grow = row0 + r;
            if (k < MSG_DIM)    x0 = messages[grow * MSG_DIM + k];
            else if (k < KDIM)  x0 = memory[(size_t)nid * MEM_DIM + (k - MSG_DIM)];
            int k1 = k + 1;
            if (k1 < MSG_DIM)   x1 = messages[grow * MSG_DIM + k1];
            else if (k1 < KDIM) x1 = memory[(size_t)nid * MEM_DIM + (k1 - MSG_DIM)];
        }
        ((uint32_t*)(xh))[idx] = pack_h(x0, x1);
    }
    __syncthreads();

    // ---- per-warp MMA main loop: 4 row tiles x own jc subset ----
    const int jc0 = (wid < 2) ? wid * 6 : 12 + (wid - 2) * 5;
    const int njw = (wid < 2) ? 6 : 5;
    const int g  = lane >> 2;
    const int tg = lane & 3;
    uint32_t ah[4];
    #pragma unroll
    for (int t = 0; t < 4; t++) {
        int rr = t * 16 + (lane & 15);
        ah[t] = smb + SM_XH + rr * (XSTR * 2) + ((lane >> 4) * 16);
    }

    for (int jcl = 0; jcl < njw; jcl++) {
        const int jc = jc0 + jcl;
        float aR[4][4] = {}, aZ[4][4] = {}, aI[4][4] = {}, aH[4][4] = {};
        const uint4* __restrict__ fp = g_Wf + ((size_t)jc * KSTEPS) * 2 * 32 + lane;

        uint4 fh  = fp[0];        // {R, Z}
        uint4 fih = fp[32];       // {I, H}
        uint32_t hA[4];
        LDSM4(hA[0], hA[1], hA[2], hA[3], ah[0]);

        #pragma unroll 1
        for (int ks = 0; ks < KSTEPS; ks++) {
            const int ksn = (ks + 1 < KSTEPS) ? ks + 1 : ks;
            uint4 fhN  = fp[(size_t)ksn * 64];
            uint4 fihN = fp[(size_t)ksn * 64 + 32];

            const bool doI = (ks < 7);       // k < 112 (zero-padded past 100)
            const bool doH = (ks >= 6);      // k >= 96 (zero-padded before 100)

            #pragma unroll
            for (int t = 0; t < 4; t++) {
                const int tn  = (t + 1) & 3;
                const int ksA = (t == 3) ? ksn : ks;
                uint32_t hN[4];
                LDSM4(hN[0], hN[1], hN[2], hN[3], ah[tn] + ksA * 32);

                MMA(aR[t], hA, fh.x, fh.y);
                MMA(aZ[t], hA, fh.z, fh.w);
                if (doI) MMA(aI[t], hA, fih.x, fih.y);
                if (doH) MMA(aH[t], hA, fih.z, fih.w);

                #pragma unroll
                for (int q = 0; q < 4; q++) hA[q] = hN[q];
            }
            fh = fhN; fih = fihN;
        }

        // ---- epilogue (h_old exact from gmem) ----
        #pragma unroll
        for (int t = 0; t < 4; t++) {
            #pragma unroll
            for (int e = 0; e < 4; e++) {
                int lr = t * 16 + g + (e >> 1) * 8;       // local row
                int j  = jc * 8 + tg * 2 + (e & 1);       // output column
                int nid = s_nid[lr];
                if (nid >= 0 && j < MEM_DIM) {
                    float Rv = aR[t][e] + g_bias[j];
                    float Zv = aZ[t][e] + g_bias[JPAD + j];
                    float Iv = aI[t][e] + g_bias[2 * JPAD + j];
                    float Hv = aH[t][e] + g_bias[3 * JPAD + j];
                    float h_old = memory[(size_t)nid * MEM_DIM + j];  // exact fp32
                    float rg = 1.f / (1.f + expf(-Rv));
                    float zg = 1.f / (1.f + expf(-Zv));
                    float ng = tanhf(Iv + rg * Hv);
                    out[(size_t)nid * MEM_DIM + j] = (1.f - zg) * ng + zg * h_old;
                }
            }
        }
    }
}

// ---------------------------------------------------------------------------
extern "C" void kernel_launch(void* const* d_in, const int* in_sizes, int n_in,
                              void* d_out, int out_size) {
    const int*   node_ids    = (const int*)  d_in[0];
    const float* messages    = (const float*)d_in[1];
    const float* timestamps  = (const float*)d_in[2];
    const float* memory      = (const float*)d_in[3];
    const float* last_update = (const float*)d_in[4];
    const float* W_ih        = (const float*)d_in[5];
    const float* W_hh        = (const float*)d_in[6];
    const float* b_ih        = (const float*)d_in[7];
    const float* b_hh        = (const float*)d_in[8];
    float* out = (float*)d_out;

    const int       n_upd   = in_sizes[0];
    const long long n_nodes = in_sizes[4];
    const long long nmem    = n_nodes * (long long)MEM_DIM;

    // One-time infra (no device memory allocation)
    static bool inited = false;
    static cudaStream_t s2;
    static cudaEvent_t evFork, evJoin;
    if (!inited) {
        cudaFuncSetAttribute(gru_mma_kernel,
                             cudaFuncAttributeMaxDynamicSharedMemorySize, SM_TOT);
        cudaStreamCreateWithFlags(&s2, cudaStreamNonBlocking);
        cudaEventCreateWithFlags(&evFork, cudaEventDisableTiming);
        cudaEventCreateWithFlags(&evJoin, cudaEventDisableTiming);
        inited = true;
    }

    prep_kernel<<<(NFRAG + 255) / 256, 256>>>(W_ih, W_hh, b_ih, b_hh);

    bool overlap = (n_upd > 0) && (n_nodes <= (long long)MASK_CAP) &&
                   (nmem % 4 == 0);

    if (overlap) {
        mask_kernel<<<(n_upd + 255) / 256, 256>>>(node_ids, n_upd);

        // fork: copies on s2, GRU on main stream, then join
        cudaEventRecord(evFork, 0);
        cudaStreamWaitEvent(s2, evFork, 0);

        long long n4 = nmem >> 2;
        copy_mem_masked<<<(unsigned)((n4 + 255) / 256), 256, 0, s2>>>(
            (const float4*)memory, (float4*)out, n4);
        copy_lu_masked<<<(unsigned)((n_nodes + 255) / 256), 256, 0, s2>>>(
            last_update, out + nmem, n_nodes);
        cudaEventRecord(evJoin, s2);

        gru_mma_kernel<<<(n_upd + MROWS - 1) / MROWS, NTH, SM_TOT>>>(
            node_ids, messages, timestamps, memory, out, n_upd, n_nodes);

        cudaStreamWaitEvent(0, evJoin, 0);
    } else {
        // serial fallback (R16 behavior)
        long long n4 = (nmem + 3) >> 2;
        copy_kernel<<<(unsigned)((n4 + 255) / 256), 256>>>(memory, out, nmem);
        long long n4b = (n_nodes + 3) >> 2;
        copy_kernel<<<(unsigned)((n4b + 255) / 256), 256>>>(last_update, out + nmem, n_nodes);
        if (n_upd > 0) {
            gru_mma_kernel<<<(n_upd + MROWS - 1) / MROWS, NTH, SM_TOT>>>(
                node_ids, messages, timestamps, memory, out, n_upd, n_nodes);
        }
    }
}